// round 12
// baseline (speedup 1.0000x reference)
#include <cuda_runtime.h>
#include <cuda_fp16.h>
#include <stdint.h>
#include <math.h>

// ---------------------------------------------------------------------------
// GNN_Encoder: 3x GCNConv (self-loops, sym-norm) + LN/leaky/residual + tanh
// B=64, N=10000, F=16, H=64, E=320000
// R11: R10 + consumer GEMMs fused into aggH epilogues via smem staging
//      (eliminates h2/h3 materialization: 328 MB + 2 launches).
// ---------------------------------------------------------------------------

namespace {
constexpr int NA = 10000;
constexpr int NF = 16;
constexpr int HD = 64;
constexpr int BT = 64;
constexpr int MR = NA * BT;        // 640000 rows ([node][batch] major)
constexpr int CH = BT * HD;        // 4096 hidden cols per node
constexpr int CF = BT * NF;        // 1024 input cols per node
constexpr int EMAX = 330000;
constexpr int NTILES = MR / 16;    // 40000 16-row mma tiles
}

// scratch (device globals; no allocation allowed)
__device__ __align__(256) __half g_h1h[MR * HD];      // h1 fp16
__device__ __align__(256) __half g_pre[MR * HD];      // pre-agg operand A (h1W2*dinv)
__device__ __align__(256) __half g_preB[MR * HD];     // pre-agg operand B (h2W3*dinv)
__device__ __align__(256) __half g_X[NA * CF];        // pre-scaled input fp16
__device__ __align__(256) __half g_AX[NA * CF];       // A·x fp16
__device__ __half g_W1t[HD * NF];   // [n][k] transposed fp16 weights
__device__ __half g_W2t[HD * HD];
__device__ __half g_W3t[HD * HD];
__device__ __half g_Wft[HD * HD];
__device__ int   g_deg[NA];
__device__ float g_dinv[NA];
__device__ int   g_rowptr[NA + 1];
__device__ int   g_fillptr[NA];
__device__ int   g_col[EMAX];

__device__ __forceinline__ float leaky(float x) {
    return x >= 0.f ? x : 0.01f * x;
}

__device__ __forceinline__ void mma16816(float c[4],
    uint32_t a0, uint32_t a1, uint32_t a2, uint32_t a3,
    uint32_t b0, uint32_t b1)
{
    asm volatile(
        "mma.sync.aligned.m16n8k16.row.col.f32.f16.f16.f32 "
        "{%0,%1,%2,%3},{%4,%5,%6,%7},{%8,%9},{%0,%1,%2,%3};"
        : "+f"(c[0]), "+f"(c[1]), "+f"(c[2]), "+f"(c[3])
        : "r"(a0), "r"(a1), "r"(a2), "r"(a3), "r"(b0), "r"(b1));
}

// ---------------- graph preprocessing ----------------

// g_deg was memset to 0; count edges by dst. First 4096 threads also convert
// weights to fp16 transposed [n][k].
__global__ void count_kernel(const int* __restrict__ ei, int E,
                             const float* __restrict__ W1,
                             const float* __restrict__ W2,
                             const float* __restrict__ W3,
                             const float* __restrict__ Wf)
{
    int i = blockIdx.x * blockDim.x + threadIdx.x;
    if (i < E) atomicAdd(&g_deg[ei[E + i]], 1);
    if (i < HD * HD) {
        int n = i / HD, k = i % HD;
        g_W2t[i] = __float2half(W2[k * HD + n]);
        g_W3t[i] = __float2half(W3[k * HD + n]);
        g_Wft[i] = __float2half(Wf[k * HD + n]);
        if (i < HD * NF) {
            int n1 = i / NF, k1 = i % NF;
            g_W1t[i] = __float2half(W1[k1 * HD + n1]);
        }
    }
}

// scan of (deg+1) -> rowptr, fillptr=rowptr+1, self-loop col entry, dinv
__global__ __launch_bounds__(1024) void scan_kernel() {
    __shared__ int warp_tot[32];
    const int tid  = threadIdx.x;
    const int lane = tid & 31;
    const int wid  = tid >> 5;
    const int base = tid * 10;

    int v[10];
    int run = 0;
#pragma unroll
    for (int k = 0; k < 10; ++k) {
        int i = base + k;
        int x = (i < NA) ? (g_deg[i] + 1) : 0;   // +1 self loop
        if (i < NA) g_dinv[i] = rsqrtf((float)x);
        run += x;
        v[k] = run;
    }
    int s = run;
#pragma unroll
    for (int off = 1; off < 32; off <<= 1) {
        int y = __shfl_up_sync(0xffffffffu, s, off);
        if (lane >= off) s += y;
    }
    if (lane == 31) warp_tot[wid] = s;
    __syncthreads();
    if (wid == 0) {
        int w = warp_tot[lane];
#pragma unroll
        for (int off = 1; off < 32; off <<= 1) {
            int y = __shfl_up_sync(0xffffffffu, w, off);
            if (lane >= off) w += y;
        }
        warp_tot[lane] = w;
    }
    __syncthreads();
    const int warp_off = (wid == 0) ? 0 : warp_tot[wid - 1];
    const int excl = warp_off + (s - run);
    if (tid == 0) g_rowptr[0] = 0;
#pragma unroll
    for (int k = 0; k < 10; ++k) {
        int i = base + k;
        if (i < NA) {
            int rbeg = excl + (k ? v[k - 1] : 0);
            g_rowptr[i + 1] = excl + v[k];
            g_col[rbeg]     = i;           // self loop first
            g_fillptr[i]    = rbeg + 1;    // edges after it
        }
    }
}

__global__ void fill_kernel(const int* __restrict__ ei, int E) {
    int i = blockIdx.x * blockDim.x + threadIdx.x;
    if (i < E) {
        int d = ei[E + i];
        int pos = atomicAdd(&g_fillptr[d], 1);
        g_col[pos] = ei[i];
    }
}

// ---------------- transpose + pre-scale (vectorized)
__global__ void transpose_kernel(const float* __restrict__ state) {
    int i = blockIdx.x * blockDim.x + threadIdx.x;
    if (i >= NA * BT) return;
    const int n = i >> 6, b = i & 63;
    const float4* sp = reinterpret_cast<const float4*>(
        state + (size_t)b * (NA * NF) + n * NF);
    const float sc = g_dinv[n];
    __half2 o[8];
#pragma unroll
    for (int q = 0; q < 4; ++q) {
        float4 u = sp[q];
        o[2 * q]     = __floats2half2_rn(u.x * sc, u.y * sc);
        o[2 * q + 1] = __floats2half2_rn(u.z * sc, u.w * sc);
    }
    float4* dp = reinterpret_cast<float4*>(g_X + (size_t)n * CF + b * NF);
    dp[0] = reinterpret_cast<const float4*>(o)[0];
    dp[1] = reinterpret_cast<const float4*>(o)[1];
}

// ---------------- conv1 aggregation: AX[d] = dinv[d] * sum_s X[s] (fp16 out)
__global__ __launch_bounds__(128) void agg16_kernel(
    const __half* __restrict__ src, __half* __restrict__ dst)
{
    const int d = blockIdx.x;
    const int c = threadIdx.x * 8;
    float acc[8];
#pragma unroll
    for (int k = 0; k < 8; ++k) acc[k] = 0.f;

    const int beg = g_rowptr[d], end = g_rowptr[d + 1];
#pragma unroll 4
    for (int j = beg; j < end; ++j) {
        const int s = g_col[j];
        float4 u = *reinterpret_cast<const float4*>(src + (size_t)s * CF + c);
        const __half2* h = reinterpret_cast<const __half2*>(&u);
#pragma unroll
        for (int k = 0; k < 4; ++k) {
            float2 f = __half22float2(h[k]);
            acc[2 * k]     += f.x;
            acc[2 * k + 1] += f.y;
        }
    }
    const float sc = g_dinv[d];
    __half2 o[4];
#pragma unroll
    for (int k = 0; k < 4; ++k)
        o[k] = __floats2half2_rn(acc[2 * k] * sc, acc[2 * k + 1] * sc);
    *reinterpret_cast<float4*>(dst + (size_t)d * CF + c) =
        *reinterpret_cast<const float4*>(o);
}

// ---------------- fused hidden aggregation + consumer GEMM
// One block per node: 256 threads, 16 cols each = full 4096-col node row.
// Phase 1 (gather + epilogue):
//   MODE 1: h2 = leaky(sum*dinv + b2) + h1
//   MODE 2: h3 = leaky(LN(sum*dinv + b3; gma,bta)) + h1
// Stage h2/h3 (fp16) in padded smem [64 rows x 72 halves], then
// Phase 2 (GEMM): 8 warps, warp w does rows tt=w>>1 (16) x nt block (w&1)*4.
//   MODE 1: out = (h2 @ W3) * dinv[node]      -> outH (fp16)
//   MODE 2: out = tanh(h3 @ Wf + bias2)       -> outF (fp32, transposed)
template <int MODE>
__global__ __launch_bounds__(256) void aggH_gemm_kernel(
    const __half* __restrict__ src,
    __half* __restrict__ outH, float* __restrict__ outF,
    const __half* __restrict__ Wt,
    const float* __restrict__ bias,
    const float* __restrict__ gma, const float* __restrict__ bta,
    const float* __restrict__ bias2)
{
    __shared__ __half sh[64 * 72];   // padded: stride 72 halves (144 B)

    const int d   = blockIdx.x;
    const int tid = threadIdx.x;
    const int c0  = tid * 16;
    const int f0  = c0 & 63;
    const int srow = c0 >> 6;        // batch row 0..63

    float acc[16];
#pragma unroll
    for (int k = 0; k < 16; ++k) acc[k] = 0.f;

    const int beg = g_rowptr[d], end = g_rowptr[d + 1];
#pragma unroll 4
    for (int j = beg; j < end; ++j) {
        const int s = g_col[j];
        const __half* row = src + (size_t)s * CH + c0;
        float4 u0 = *reinterpret_cast<const float4*>(row);
        float4 u1 = *reinterpret_cast<const float4*>(row + 8);
        const __half2* h0 = reinterpret_cast<const __half2*>(&u0);
        const __half2* h1 = reinterpret_cast<const __half2*>(&u1);
#pragma unroll
        for (int k = 0; k < 4; ++k) {
            float2 a = __half22float2(h0[k]);
            float2 b = __half22float2(h1[k]);
            acc[2 * k]         += a.x;
            acc[2 * k + 1]     += a.y;
            acc[8 + 2 * k]     += b.x;
            acc[8 + 2 * k + 1] += b.y;
        }
    }

    const float sc = g_dinv[d];
    float v[16];
#pragma unroll
    for (int k = 0; k < 16; ++k) v[k] = fmaf(acc[k], sc, bias[f0 + k]);

    // fp16 h1 residual
    const __half* h1p = g_h1h + (size_t)d * CH + c0;
    float4 r0 = *reinterpret_cast<const float4*>(h1p);
    float4 r1 = *reinterpret_cast<const float4*>(h1p + 8);
    float h1v[16];
    {
        const __half2* p0 = reinterpret_cast<const __half2*>(&r0);
        const __half2* p1 = reinterpret_cast<const __half2*>(&r1);
#pragma unroll
        for (int k = 0; k < 4; ++k) {
            float2 a = __half22float2(p0[k]);
            float2 b = __half22float2(p1[k]);
            h1v[2 * k]         = a.x;
            h1v[2 * k + 1]     = a.y;
            h1v[8 + 2 * k]     = b.x;
            h1v[8 + 2 * k + 1] = b.y;
        }
    }

    float out[16];
    if (MODE == 1) {
#pragma unroll
        for (int k = 0; k < 16; ++k) out[k] = leaky(v[k]) + h1v[k];
    } else {
        float s1 = 0.f, s2 = 0.f;
#pragma unroll
        for (int k = 0; k < 16; ++k) { s1 += v[k]; s2 += v[k] * v[k]; }
        s1 += __shfl_xor_sync(0xffffffffu, s1, 1);
        s2 += __shfl_xor_sync(0xffffffffu, s2, 1);
        s1 += __shfl_xor_sync(0xffffffffu, s1, 2);
        s2 += __shfl_xor_sync(0xffffffffu, s2, 2);
        const float mean = s1 * (1.f / 64.f);
        const float var  = fmaf(s2, 1.f / 64.f, -mean * mean);
        const float rs   = rsqrtf(var + 1e-5f);
#pragma unroll
        for (int k = 0; k < 16; ++k)
            out[k] = leaky(fmaf((v[k] - mean) * rs, gma[f0 + k], bta[f0 + k])) + h1v[k];
    }

    // stage fp16 to padded smem (numerics identical to old buffer round trip)
    {
        __half2 o[8];
#pragma unroll
        for (int k = 0; k < 8; ++k)
            o[k] = __floats2half2_rn(out[2 * k], out[2 * k + 1]);
        float4* sp = reinterpret_cast<float4*>(sh + srow * 72 + f0);
        sp[0] = reinterpret_cast<const float4*>(o)[0];
        sp[1] = reinterpret_cast<const float4*>(o)[1];
    }
    __syncthreads();

    // ---------------- GEMM phase ----------------
    const int w    = tid >> 5;
    const int lane = tid & 31;
    const int g = lane >> 2, t = lane & 3;
    const int tt  = w >> 1;          // row tile 0..3 (rows tt*16..tt*16+15)
    const int ntb = (w & 1) * 4;     // n-tile offset: 4 of 8

    uint32_t B0[4][4], B1[4][4];
    const uint32_t* wp = reinterpret_cast<const uint32_t*>(Wt);
#pragma unroll
    for (int kk = 0; kk < 4; ++kk)
#pragma unroll
        for (int j = 0; j < 4; ++j) {
            int n = (ntb + j) * 8 + g;
            B0[kk][j] = wp[(n * 64 + kk * 16 + t * 2) >> 1];
            B1[kk][j] = wp[(n * 64 + kk * 16 + 8 + t * 2) >> 1];
        }

    float C[4][4];
#pragma unroll
    for (int j = 0; j < 4; ++j) { C[j][0] = C[j][1] = C[j][2] = C[j][3] = 0.f; }

#pragma unroll
    for (int kk = 0; kk < 4; ++kk) {
        const __half* base = sh + (tt * 16) * 72 + kk * 16;
        uint32_t a0 = *reinterpret_cast<const uint32_t*>(base + g * 72 + t * 2);
        uint32_t a1 = *reinterpret_cast<const uint32_t*>(base + (g + 8) * 72 + t * 2);
        uint32_t a2 = *reinterpret_cast<const uint32_t*>(base + g * 72 + 8 + t * 2);
        uint32_t a3 = *reinterpret_cast<const uint32_t*>(base + (g + 8) * 72 + 8 + t * 2);
#pragma unroll
        for (int j = 0; j < 4; ++j)
            mma16816(C[j], a0, a1, a2, a3, B0[kk][j], B1[kk][j]);
    }

    if (MODE == 1) {
        const float s = g_dinv[d];
        const size_t ra = (size_t)(d * 64 + tt * 16 + g) * 64;
        const size_t rb = ra + (size_t)8 * 64;
#pragma unroll
        for (int j = 0; j < 4; ++j) {
            int col = (ntb + j) * 8 + t * 2;
            *reinterpret_cast<__half2*>(outH + ra + col) =
                __floats2half2_rn(C[j][0] * s, C[j][1] * s);
            *reinterpret_cast<__half2*>(outH + rb + col) =
                __floats2half2_rn(C[j][2] * s, C[j][3] * s);
        }
    } else {
        const int ba = tt * 16 + g;       // batch rows
        float* oa = outF + (size_t)ba * (NA * HD) + (size_t)d * 64;
        float* ob = outF + (size_t)(ba + 8) * (NA * HD) + (size_t)d * 64;
#pragma unroll
        for (int j = 0; j < 4; ++j) {
            int col = (ntb + j) * 8 + t * 2;
            float2 bv = *reinterpret_cast<const float2*>(bias2 + col);
            *reinterpret_cast<float2*>(oa + col) =
                make_float2(tanhf(C[j][0] + bv.x), tanhf(C[j][1] + bv.y));
            *reinterpret_cast<float2*>(ob + col) =
                make_float2(tanhf(C[j][2] + bv.x), tanhf(C[j][3] + bv.y));
        }
    }
}

// ---------------- HMMA GEMM K=16 + bias + LN + leaky -> h1 fp16,
// then fused W2 GEMM on the in-register h1 (C-frag == A-frag layout),
// epilogue * dinv[node] -> g_pre fp16
__global__ __launch_bounds__(128) void hgemm16_ln_w2_kernel(
    const __half* __restrict__ in, const float* __restrict__ bias,
    const float* __restrict__ gma, const float* __restrict__ bta,
    __half* __restrict__ out_h1, __half* __restrict__ out_pre)
{
    const int lane = threadIdx.x & 31;
    const int g = lane >> 2, t = lane & 3;

    uint32_t B0[8], B1[8];
    {
        const uint32_t* wp = reinterpret_cast<const uint32_t*>(g_W1t);
#pragma unroll
        for (int nt = 0; nt < 8; ++nt) {
            B0[nt] = wp[((nt * 8 + g) * 16 + t * 2) >> 1];
            B1[nt] = wp[((nt * 8 + g) * 16 + 8 + t * 2) >> 1];
        }
    }
    uint32_t W20[4][8], W21[4][8];
    {
        const uint32_t* wp = reinterpret_cast<const uint32_t*>(g_W2t);
#pragma unroll
        for (int kk = 0; kk < 4; ++kk)
#pragma unroll
            for (int nt = 0; nt < 8; ++nt) {
                W20[kk][nt] = wp[((nt * 8 + g) * 64 + kk * 16 + t * 2) >> 1];
                W21[kk][nt] = wp[((nt * 8 + g) * 64 + kk * 16 + 8 + t * 2) >> 1];
            }
    }

    const int warp = (blockIdx.x * blockDim.x + threadIdx.x) >> 5;
    const int nw   = (gridDim.x * blockDim.x) >> 5;
    for (int tile = warp; tile < NTILES; tile += nw) {
        const int rb = tile * 16;
        const uint32_t* ap = reinterpret_cast<const uint32_t*>(in + (size_t)rb * 16);
        uint32_t a0 = ap[(g * 16 + t * 2) >> 1];
        uint32_t a1 = ap[((g + 8) * 16 + t * 2) >> 1];
        uint32_t a2 = ap[(g * 16 + 8 + t * 2) >> 1];
        uint32_t a3 = ap[((g + 8) * 16 + 8 + t * 2) >> 1];

        float C[8][4];
#pragma unroll
        for (int nt = 0; nt < 8; ++nt) { C[nt][0] = C[nt][1] = C[nt][2] = C[nt][3] = 0.f; }
#pragma unroll
        for (int nt = 0; nt < 8; ++nt)
            mma16816(C[nt], a0, a1, a2, a3, B0[nt], B1[nt]);

        float va[16], vb[16];
#pragma unroll
        for (int nt = 0; nt < 8; ++nt) {
            float2 bv = *reinterpret_cast<const float2*>(bias + nt * 8 + t * 2);
            va[2 * nt]     = C[nt][0] + bv.x;
            va[2 * nt + 1] = C[nt][1] + bv.y;
            vb[2 * nt]     = C[nt][2] + bv.x;
            vb[2 * nt + 1] = C[nt][3] + bv.y;
        }
        float s1a = 0.f, s2a = 0.f, s1b = 0.f, s2b = 0.f;
#pragma unroll
        for (int k = 0; k < 16; ++k) {
            s1a += va[k]; s2a += va[k] * va[k];
            s1b += vb[k]; s2b += vb[k] * vb[k];
        }
#pragma unroll
        for (int off = 1; off <= 2; off <<= 1) {
            s1a += __shfl_xor_sync(0xffffffffu, s1a, off);
            s2a += __shfl_xor_sync(0xffffffffu, s2a, off);
            s1b += __shfl_xor_sync(0xffffffffu, s1b, off);
            s2b += __shfl_xor_sync(0xffffffffu, s2b, off);
        }
        const float ma = s1a * (1.f / 64.f);
        const float ra = rsqrtf(fmaf(s2a, 1.f / 64.f, -ma * ma) + 1e-5f);
        const float mb = s1b * (1.f / 64.f);
        const float rbv = rsqrtf(fmaf(s2b, 1.f / 64.f, -mb * mb) + 1e-5f);

        uint32_t ha[8], hb[8];
#pragma unroll
        for (int nt = 0; nt < 8; ++nt) {
            float2 gv = *reinterpret_cast<const float2*>(gma + nt * 8 + t * 2);
            float2 ev = *reinterpret_cast<const float2*>(bta + nt * 8 + t * 2);
            float x0 = leaky(fmaf((va[2 * nt]     - ma) * ra, gv.x, ev.x));
            float x1 = leaky(fmaf((va[2 * nt + 1] - ma) * ra, gv.y, ev.y));
            float y0 = leaky(fmaf((vb[2 * nt]     - mb) * rbv, gv.x, ev.x));
            float y1 = leaky(fmaf((vb[2 * nt + 1] - mb) * rbv, gv.y, ev.y));
            __half2 hx = __floats2half2_rn(x0, x1);
            __half2 hy = __floats2half2_rn(y0, y1);
            ha[nt] = *reinterpret_cast<const uint32_t*>(&hx);
            hb[nt] = *reinterpret_cast<const uint32_t*>(&hy);
        }
        __half* oa16 = out_h1 + (size_t)(rb + g) * 64 + t * 2;
        __half* ob16 = out_h1 + (size_t)(rb + g + 8) * 64 + t * 2;
#pragma unroll
        for (int nt = 0; nt < 8; ++nt) {
            *reinterpret_cast<uint32_t*>(oa16 + nt * 8) = ha[nt];
            *reinterpret_cast<uint32_t*>(ob16 + nt * 8) = hb[nt];
        }

        float C2[8][4];
#pragma unroll
        for (int nt = 0; nt < 8; ++nt) { C2[nt][0] = C2[nt][1] = C2[nt][2] = C2[nt][3] = 0.f; }
#pragma unroll
        for (int kk = 0; kk < 4; ++kk) {
#pragma unroll
            for (int nt = 0; nt < 8; ++nt)
                mma16816(C2[nt], ha[2 * kk], hb[2 * kk], ha[2 * kk + 1], hb[2 * kk + 1],
                         W20[kk][nt], W21[kk][nt]);
        }

        const float s = g_dinv[rb >> 6];
        __half* pa = out_pre + (size_t)(rb + g) * 64 + t * 2;
        __half* pb = out_pre + (size_t)(rb + g + 8) * 64 + t * 2;
#pragma unroll
        for (int nt = 0; nt < 8; ++nt) {
            *reinterpret_cast<__half2*>(pa + nt * 8) =
                __floats2half2_rn(C2[nt][0] * s, C2[nt][1] * s);
            *reinterpret_cast<__half2*>(pb + nt * 8) =
                __floats2half2_rn(C2[nt][2] * s, C2[nt][3] * s);
        }
    }
}

// ---------------------------------------------------------------------------

extern "C" void kernel_launch(void* const* d_in, const int* in_sizes, int n_in,
                              void* d_out, int out_size)
{
    const float* state = (const float*)d_in[0];
    const int*   ei    = (const int*)d_in[1];
    const float* W1  = (const float*)d_in[5];
    const float* b1  = (const float*)d_in[6];
    const float* W2  = (const float*)d_in[7];
    const float* b2  = (const float*)d_in[8];
    const float* W3  = (const float*)d_in[9];
    const float* b3  = (const float*)d_in[10];
    const float* g1  = (const float*)d_in[11];
    const float* be1 = (const float*)d_in[12];
    const float* g3  = (const float*)d_in[13];
    const float* be3 = (const float*)d_in[14];
    const float* Wf  = (const float*)d_in[15];
    const float* bf  = (const float*)d_in[16];
    float* out = (float*)d_out;

    const int E = in_sizes[1] / 2;

    __half *pH1h, *pPre, *pPreB, *pX, *pAX;
    cudaGetSymbolAddress((void**)&pH1h, g_h1h);
    cudaGetSymbolAddress((void**)&pPre, g_pre);
    cudaGetSymbolAddress((void**)&pPreB, g_preB);
    cudaGetSymbolAddress((void**)&pX,   g_X);
    cudaGetSymbolAddress((void**)&pAX,  g_AX);

    __half *pW3t, *pWft;
    cudaGetSymbolAddress((void**)&pW3t, g_W3t);
    cudaGetSymbolAddress((void**)&pWft, g_Wft);
    int* pDeg;
    cudaGetSymbolAddress((void**)&pDeg, g_deg);

    // graph preprocessing (CSR by dst; self-loops emitted by scan),
    // weight fp16 prep merged into count
    cudaMemsetAsync(pDeg, 0, NA * sizeof(int));
    count_kernel<<<(E + 255) / 256, 256>>>(ei, E, W1, W2, W3, Wf);
    scan_kernel<<<1, 1024>>>();
    fill_kernel<<<(E + 255) / 256, 256>>>(ei, E);

    // transpose input
    transpose_kernel<<<(NA * BT + 255) / 256, 256>>>(state);

    // conv1 = (A x) W1, + fused W2 GEMM producing conv2's pre-agg operand
    agg16_kernel<<<NA, 128>>>(pX, pAX);
    hgemm16_ln_w2_kernel<<<4736, 128>>>(pAX, b1, g1, be1, pH1h, pPre);

    // conv2 agg + epilogue + fused W3 GEMM -> preB (= h2 W3 * dinv)
    aggH_gemm_kernel<1><<<NA, 256>>>(pPre, pPreB, nullptr, pW3t,
                                     b2, nullptr, nullptr, nullptr);

    // conv3 agg + LN epilogue + fused final GEMM + tanh -> out (transposed)
    aggH_gemm_kernel<2><<<NA, 256>>>(pPreB, nullptr, out, pWft,
                                     b3, g3, be3, bf);
}

// round 15
// speedup vs baseline: 1.1011x; 1.1011x over previous
#include <cuda_runtime.h>
#include <cuda_fp16.h>
#include <stdint.h>
#include <math.h>

// ---------------------------------------------------------------------------
// GNN_Encoder: 3x GCNConv (self-loops, sym-norm) + LN/leaky/residual + tanh
// B=64, N=10000, F=16, H=64, E=320000
// R12 (= R10 revert + fill/transpose merged): HMMA GEMMs (W2 fused into
//     conv1 GEMM), fp16 inter-stage buffers, fused epilogues. R11's
//     aggH+GEMM fusion reverted (register pressure killed gather MLP).
// ---------------------------------------------------------------------------

namespace {
constexpr int NA = 10000;
constexpr int NF = 16;
constexpr int HD = 64;
constexpr int BT = 64;
constexpr int MR = NA * BT;        // 640000 rows ([node][batch] major)
constexpr int CH = BT * HD;        // 4096 hidden cols per node
constexpr int CF = BT * NF;        // 1024 input cols per node
constexpr int EMAX = 330000;
constexpr int NTILES = MR / 16;    // 40000 16-row mma tiles
}

// scratch (device globals; no allocation allowed)
__device__ __align__(256) __half g_h1h[MR * HD];      // h1 fp16
__device__ __align__(256) __half g_h2h[MR * HD];      // h2 fp16
__device__ __align__(256) __half g_h3h[MR * HD];      // h3 fp16
__device__ __align__(256) __half g_pre[MR * HD];      // pre-agg operand fp16
__device__ __align__(256) __half g_X[NA * CF];        // pre-scaled input fp16
__device__ __align__(256) __half g_AX[NA * CF];       // A·x fp16
__device__ __half g_W1t[HD * NF];   // [n][k] transposed fp16 weights
__device__ __half g_W2t[HD * HD];
__device__ __half g_W3t[HD * HD];
__device__ __half g_Wft[HD * HD];
__device__ int   g_deg[NA];
__device__ float g_dinv[NA];
__device__ int   g_rowptr[NA + 1];
__device__ int   g_fillptr[NA];
__device__ int   g_col[EMAX];

__device__ __forceinline__ float leaky(float x) {
    return x >= 0.f ? x : 0.01f * x;
}

__device__ __forceinline__ void mma16816(float c[4],
    uint32_t a0, uint32_t a1, uint32_t a2, uint32_t a3,
    uint32_t b0, uint32_t b1)
{
    asm volatile(
        "mma.sync.aligned.m16n8k16.row.col.f32.f16.f16.f32 "
        "{%0,%1,%2,%3},{%4,%5,%6,%7},{%8,%9},{%0,%1,%2,%3};"
        : "+f"(c[0]), "+f"(c[1]), "+f"(c[2]), "+f"(c[3])
        : "r"(a0), "r"(a1), "r"(a2), "r"(a3), "r"(b0), "r"(b1));
}

// ---------------- graph preprocessing ----------------

// g_deg was memset to 0; count edges by dst. First 4096 threads also convert
// weights to fp16 transposed [n][k] (independent work, saves a launch).
__global__ void count_kernel(const int* __restrict__ ei, int E,
                             const float* __restrict__ W1,
                             const float* __restrict__ W2,
                             const float* __restrict__ W3,
                             const float* __restrict__ Wf)
{
    int i = blockIdx.x * blockDim.x + threadIdx.x;
    if (i < E) atomicAdd(&g_deg[ei[E + i]], 1);
    if (i < HD * HD) {
        int n = i / HD, k = i % HD;
        g_W2t[i] = __float2half(W2[k * HD + n]);
        g_W3t[i] = __float2half(W3[k * HD + n]);
        g_Wft[i] = __float2half(Wf[k * HD + n]);
        if (i < HD * NF) {
            int n1 = i / NF, k1 = i % NF;
            g_W1t[i] = __float2half(W1[k1 * HD + n1]);
        }
    }
}

// scan of (deg+1) -> rowptr, fillptr=rowptr+1, self-loop col entry, dinv
__global__ __launch_bounds__(1024) void scan_kernel() {
    __shared__ int warp_tot[32];
    const int tid  = threadIdx.x;
    const int lane = tid & 31;
    const int wid  = tid >> 5;
    const int base = tid * 10;

    int v[10];
    int run = 0;
#pragma unroll
    for (int k = 0; k < 10; ++k) {
        int i = base + k;
        int x = (i < NA) ? (g_deg[i] + 1) : 0;   // +1 self loop
        if (i < NA) g_dinv[i] = rsqrtf((float)x);
        run += x;
        v[k] = run;
    }
    int s = run;
#pragma unroll
    for (int off = 1; off < 32; off <<= 1) {
        int y = __shfl_up_sync(0xffffffffu, s, off);
        if (lane >= off) s += y;
    }
    if (lane == 31) warp_tot[wid] = s;
    __syncthreads();
    if (wid == 0) {
        int w = warp_tot[lane];
#pragma unroll
        for (int off = 1; off < 32; off <<= 1) {
            int y = __shfl_up_sync(0xffffffffu, w, off);
            if (lane >= off) w += y;
        }
        warp_tot[lane] = w;
    }
    __syncthreads();
    const int warp_off = (wid == 0) ? 0 : warp_tot[wid - 1];
    const int excl = warp_off + (s - run);
    if (tid == 0) g_rowptr[0] = 0;
#pragma unroll
    for (int k = 0; k < 10; ++k) {
        int i = base + k;
        if (i < NA) {
            int rbeg = excl + (k ? v[k - 1] : 0);
            g_rowptr[i + 1] = excl + v[k];
            g_col[rbeg]     = i;           // self loop first
            g_fillptr[i]    = rbeg + 1;    // edges after it
        }
    }
}

// fill CSR cols (first E lanes) + vectorized transpose/pre-scale (all lanes).
// Both depend only on scan_kernel; merging saves a launch and overlaps
// fill's atomic latency with transpose's streaming loads.
__global__ void fill_transpose_kernel(const int* __restrict__ ei, int E,
                                      const float* __restrict__ state)
{
    int i = blockIdx.x * blockDim.x + threadIdx.x;
    if (i < E) {
        int d = ei[E + i];
        int pos = atomicAdd(&g_fillptr[d], 1);
        g_col[pos] = ei[i];
    }
    if (i < NA * BT) {
        const int n = i >> 6, b = i & 63;
        const float4* sp = reinterpret_cast<const float4*>(
            state + (size_t)b * (NA * NF) + n * NF);
        const float sc = g_dinv[n];
        __half2 o[8];
#pragma unroll
        for (int q = 0; q < 4; ++q) {
            float4 u = sp[q];
            o[2 * q]     = __floats2half2_rn(u.x * sc, u.y * sc);
            o[2 * q + 1] = __floats2half2_rn(u.z * sc, u.w * sc);
        }
        float4* dp = reinterpret_cast<float4*>(g_X + (size_t)n * CF + b * NF);
        dp[0] = reinterpret_cast<const float4*>(o)[0];
        dp[1] = reinterpret_cast<const float4*>(o)[1];
    }
}

// ---------------- conv1 aggregation: AX[d] = dinv[d] * sum_s X[s] (fp16 out)
__global__ __launch_bounds__(128) void agg16_kernel(
    const __half* __restrict__ src, __half* __restrict__ dst)
{
    const int d = blockIdx.x;
    const int c = threadIdx.x * 8;
    float acc[8];
#pragma unroll
    for (int k = 0; k < 8; ++k) acc[k] = 0.f;

    const int beg = g_rowptr[d], end = g_rowptr[d + 1];
#pragma unroll 4
    for (int j = beg; j < end; ++j) {
        const int s = g_col[j];
        float4 u = *reinterpret_cast<const float4*>(src + (size_t)s * CF + c);
        const __half2* h = reinterpret_cast<const __half2*>(&u);
#pragma unroll
        for (int k = 0; k < 4; ++k) {
            float2 f = __half22float2(h[k]);
            acc[2 * k]     += f.x;
            acc[2 * k + 1] += f.y;
        }
    }
    const float sc = g_dinv[d];
    __half2 o[4];
#pragma unroll
    for (int k = 0; k < 4; ++k)
        o[k] = __floats2half2_rn(acc[2 * k] * sc, acc[2 * k + 1] * sc);
    *reinterpret_cast<float4*>(dst + (size_t)d * CF + c) =
        *reinterpret_cast<const float4*>(o);
}

// ---------------- hidden aggregation (4096 fp16 cols, 2 chunks of 2048)
// MODE 1: +b2, leaky, +h1 -> h2 fp16
// MODE 2: +b3, LN(g3,be3), leaky, +h1 -> h3 fp16
template <int MODE>
__global__ __launch_bounds__(128) void aggH_kernel(
    const __half* __restrict__ src, __half* __restrict__ dst,
    const float* __restrict__ bias,
    const float* __restrict__ gma, const float* __restrict__ bta)
{
    const int d  = blockIdx.x;
    const int c0 = blockIdx.y * 2048 + threadIdx.x * 16;
    const int f0 = c0 & 63;

    float acc[16];
#pragma unroll
    for (int k = 0; k < 16; ++k) acc[k] = 0.f;

    const int beg = g_rowptr[d], end = g_rowptr[d + 1];
#pragma unroll 4
    for (int j = beg; j < end; ++j) {
        const int s = g_col[j];
        const __half* row = src + (size_t)s * CH + c0;
        float4 u0 = *reinterpret_cast<const float4*>(row);
        float4 u1 = *reinterpret_cast<const float4*>(row + 8);
        const __half2* h0 = reinterpret_cast<const __half2*>(&u0);
        const __half2* h1 = reinterpret_cast<const __half2*>(&u1);
#pragma unroll
        for (int k = 0; k < 4; ++k) {
            float2 a = __half22float2(h0[k]);
            float2 b = __half22float2(h1[k]);
            acc[2 * k]         += a.x;
            acc[2 * k + 1]     += a.y;
            acc[8 + 2 * k]     += b.x;
            acc[8 + 2 * k + 1] += b.y;
        }
    }

    const float sc = g_dinv[d];
    float v[16];
#pragma unroll
    for (int k = 0; k < 16; ++k) v[k] = fmaf(acc[k], sc, bias[f0 + k]);

    // fp16 h1 residual (16 halves = 2x float4)
    const __half* h1p = g_h1h + (size_t)d * CH + c0;
    float4 r0 = *reinterpret_cast<const float4*>(h1p);
    float4 r1 = *reinterpret_cast<const float4*>(h1p + 8);
    float h1v[16];
    {
        const __half2* p0 = reinterpret_cast<const __half2*>(&r0);
        const __half2* p1 = reinterpret_cast<const __half2*>(&r1);
#pragma unroll
        for (int k = 0; k < 4; ++k) {
            float2 a = __half22float2(p0[k]);
            float2 b = __half22float2(p1[k]);
            h1v[2 * k]         = a.x;
            h1v[2 * k + 1]     = a.y;
            h1v[8 + 2 * k]     = b.x;
            h1v[8 + 2 * k + 1] = b.y;
        }
    }

    float out[16];
    if (MODE == 1) {
#pragma unroll
        for (int k = 0; k < 16; ++k) out[k] = leaky(v[k]) + h1v[k];
    } else {
        float s1 = 0.f, s2 = 0.f;
#pragma unroll
        for (int k = 0; k < 16; ++k) { s1 += v[k]; s2 += v[k] * v[k]; }
        s1 += __shfl_xor_sync(0xffffffffu, s1, 1);
        s2 += __shfl_xor_sync(0xffffffffu, s2, 1);
        s1 += __shfl_xor_sync(0xffffffffu, s1, 2);
        s2 += __shfl_xor_sync(0xffffffffu, s2, 2);
        const float mean = s1 * (1.f / 64.f);
        const float var  = fmaf(s2, 1.f / 64.f, -mean * mean);
        const float rs   = rsqrtf(var + 1e-5f);
#pragma unroll
        for (int k = 0; k < 16; ++k)
            out[k] = leaky(fmaf((v[k] - mean) * rs, gma[f0 + k], bta[f0 + k])) + h1v[k];
    }

    __half2 o[8];
#pragma unroll
    for (int k = 0; k < 8; ++k)
        o[k] = __floats2half2_rn(out[2 * k], out[2 * k + 1]);
    float4* op = reinterpret_cast<float4*>(dst + (size_t)d * CH + c0);
    op[0] = reinterpret_cast<const float4*>(o)[0];
    op[1] = reinterpret_cast<const float4*>(o)[1];
}

// ---------------- HMMA GEMM K=16 + bias + LN + leaky -> h1 fp16,
// then fused W2 GEMM on the in-register h1 (C-frag == A-frag layout),
// epilogue * dinv[node] -> g_pre fp16
__global__ __launch_bounds__(128) void hgemm16_ln_w2_kernel(
    const __half* __restrict__ in, const float* __restrict__ bias,
    const float* __restrict__ gma, const float* __restrict__ bta,
    __half* __restrict__ out_h1, __half* __restrict__ out_pre)
{
    const int lane = threadIdx.x & 31;
    const int g = lane >> 2, t = lane & 3;

    uint32_t B0[8], B1[8];
    {
        const uint32_t* wp = reinterpret_cast<const uint32_t*>(g_W1t);
#pragma unroll
        for (int nt = 0; nt < 8; ++nt) {
            B0[nt] = wp[((nt * 8 + g) * 16 + t * 2) >> 1];
            B1[nt] = wp[((nt * 8 + g) * 16 + 8 + t * 2) >> 1];
        }
    }
    uint32_t W20[4][8], W21[4][8];
    {
        const uint32_t* wp = reinterpret_cast<const uint32_t*>(g_W2t);
#pragma unroll
        for (int kk = 0; kk < 4; ++kk)
#pragma unroll
            for (int nt = 0; nt < 8; ++nt) {
                W20[kk][nt] = wp[((nt * 8 + g) * 64 + kk * 16 + t * 2) >> 1];
                W21[kk][nt] = wp[((nt * 8 + g) * 64 + kk * 16 + 8 + t * 2) >> 1];
            }
    }

    const int warp = (blockIdx.x * blockDim.x + threadIdx.x) >> 5;
    const int nw   = (gridDim.x * blockDim.x) >> 5;
    for (int tile = warp; tile < NTILES; tile += nw) {
        const int rb = tile * 16;
        const uint32_t* ap = reinterpret_cast<const uint32_t*>(in + (size_t)rb * 16);
        uint32_t a0 = ap[(g * 16 + t * 2) >> 1];
        uint32_t a1 = ap[((g + 8) * 16 + t * 2) >> 1];
        uint32_t a2 = ap[(g * 16 + 8 + t * 2) >> 1];
        uint32_t a3 = ap[((g + 8) * 16 + 8 + t * 2) >> 1];

        float C[8][4];
#pragma unroll
        for (int nt = 0; nt < 8; ++nt) { C[nt][0] = C[nt][1] = C[nt][2] = C[nt][3] = 0.f; }
#pragma unroll
        for (int nt = 0; nt < 8; ++nt)
            mma16816(C[nt], a0, a1, a2, a3, B0[nt], B1[nt]);

        float va[16], vb[16];
#pragma unroll
        for (int nt = 0; nt < 8; ++nt) {
            float2 bv = *reinterpret_cast<const float2*>(bias + nt * 8 + t * 2);
            va[2 * nt]     = C[nt][0] + bv.x;
            va[2 * nt + 1] = C[nt][1] + bv.y;
            vb[2 * nt]     = C[nt][2] + bv.x;
            vb[2 * nt + 1] = C[nt][3] + bv.y;
        }
        float s1a = 0.f, s2a = 0.f, s1b = 0.f, s2b = 0.f;
#pragma unroll
        for (int k = 0; k < 16; ++k) {
            s1a += va[k]; s2a += va[k] * va[k];
            s1b += vb[k]; s2b += vb[k] * vb[k];
        }
#pragma unroll
        for (int off = 1; off <= 2; off <<= 1) {
            s1a += __shfl_xor_sync(0xffffffffu, s1a, off);
            s2a += __shfl_xor_sync(0xffffffffu, s2a, off);
            s1b += __shfl_xor_sync(0xffffffffu, s1b, off);
            s2b += __shfl_xor_sync(0xffffffffu, s2b, off);
        }
        const float ma = s1a * (1.f / 64.f);
        const float ra = rsqrtf(fmaf(s2a, 1.f / 64.f, -ma * ma) + 1e-5f);
        const float mb = s1b * (1.f / 64.f);
        const float rbv = rsqrtf(fmaf(s2b, 1.f / 64.f, -mb * mb) + 1e-5f);

        uint32_t ha[8], hb[8];
#pragma unroll
        for (int nt = 0; nt < 8; ++nt) {
            float2 gv = *reinterpret_cast<const float2*>(gma + nt * 8 + t * 2);
            float2 ev = *reinterpret_cast<const float2*>(bta + nt * 8 + t * 2);
            float x0 = leaky(fmaf((va[2 * nt]     - ma) * ra, gv.x, ev.x));
            float x1 = leaky(fmaf((va[2 * nt + 1] - ma) * ra, gv.y, ev.y));
            float y0 = leaky(fmaf((vb[2 * nt]     - mb) * rbv, gv.x, ev.x));
            float y1 = leaky(fmaf((vb[2 * nt + 1] - mb) * rbv, gv.y, ev.y));
            __half2 hx = __floats2half2_rn(x0, x1);
            __half2 hy = __floats2half2_rn(y0, y1);
            ha[nt] = *reinterpret_cast<const uint32_t*>(&hx);
            hb[nt] = *reinterpret_cast<const uint32_t*>(&hy);
        }
        __half* oa16 = out_h1 + (size_t)(rb + g) * 64 + t * 2;
        __half* ob16 = out_h1 + (size_t)(rb + g + 8) * 64 + t * 2;
#pragma unroll
        for (int nt = 0; nt < 8; ++nt) {
            *reinterpret_cast<uint32_t*>(oa16 + nt * 8) = ha[nt];
            *reinterpret_cast<uint32_t*>(ob16 + nt * 8) = hb[nt];
        }

        float C2[8][4];
#pragma unroll
        for (int nt = 0; nt < 8; ++nt) { C2[nt][0] = C2[nt][1] = C2[nt][2] = C2[nt][3] = 0.f; }
#pragma unroll
        for (int kk = 0; kk < 4; ++kk) {
#pragma unroll
            for (int nt = 0; nt < 8; ++nt)
                mma16816(C2[nt], ha[2 * kk], hb[2 * kk], ha[2 * kk + 1], hb[2 * kk + 1],
                         W20[kk][nt], W21[kk][nt]);
        }

        const float s = g_dinv[rb >> 6];
        __half* pa = out_pre + (size_t)(rb + g) * 64 + t * 2;
        __half* pb = out_pre + (size_t)(rb + g + 8) * 64 + t * 2;
#pragma unroll
        for (int nt = 0; nt < 8; ++nt) {
            *reinterpret_cast<__half2*>(pa + nt * 8) =
                __floats2half2_rn(C2[nt][0] * s, C2[nt][1] * s);
            *reinterpret_cast<__half2*>(pb + nt * 8) =
                __floats2half2_rn(C2[nt][2] * s, C2[nt][3] * s);
        }
    }
}

// ---------------- HMMA GEMM K=64, epilogue * dinv[node] -> fp16
__global__ __launch_bounds__(128) void hgemm64_kernel(
    const __half* __restrict__ in, const __half* __restrict__ Wt,
    __half* __restrict__ out)
{
    const int lane = threadIdx.x & 31;
    const int g = lane >> 2, t = lane & 3;

    uint32_t B0[4][8], B1[4][8];
    const uint32_t* wp = reinterpret_cast<const uint32_t*>(Wt);
#pragma unroll
    for (int kk = 0; kk < 4; ++kk)
#pragma unroll
        for (int nt = 0; nt < 8; ++nt) {
            B0[kk][nt] = wp[((nt * 8 + g) * 64 + kk * 16 + t * 2) >> 1];
            B1[kk][nt] = wp[((nt * 8 + g) * 64 + kk * 16 + 8 + t * 2) >> 1];
        }

    const int warp = (blockIdx.x * blockDim.x + threadIdx.x) >> 5;
    const int nw   = (gridDim.x * blockDim.x) >> 5;
    for (int tile = warp; tile < NTILES; tile += nw) {
        const int rb = tile * 16;
        const uint32_t* ap = reinterpret_cast<const uint32_t*>(in + (size_t)rb * 64);

        float C[8][4];
#pragma unroll
        for (int nt = 0; nt < 8; ++nt) { C[nt][0] = C[nt][1] = C[nt][2] = C[nt][3] = 0.f; }
#pragma unroll
        for (int kk = 0; kk < 4; ++kk) {
            uint32_t a0 = ap[(g * 64 + kk * 16 + t * 2) >> 1];
            uint32_t a1 = ap[((g + 8) * 64 + kk * 16 + t * 2) >> 1];
            uint32_t a2 = ap[(g * 64 + kk * 16 + 8 + t * 2) >> 1];
            uint32_t a3 = ap[((g + 8) * 64 + kk * 16 + 8 + t * 2) >> 1];
#pragma unroll
            for (int nt = 0; nt < 8; ++nt)
                mma16816(C[nt], a0, a1, a2, a3, B0[kk][nt], B1[kk][nt]);
        }

        const float s = g_dinv[rb >> 6];
        __half* oa = out + (size_t)(rb + g) * 64 + t * 2;
        __half* ob = out + (size_t)(rb + g + 8) * 64 + t * 2;
#pragma unroll
        for (int nt = 0; nt < 8; ++nt) {
            *reinterpret_cast<__half2*>(oa + nt * 8) =
                __floats2half2_rn(C[nt][0] * s, C[nt][1] * s);
            *reinterpret_cast<__half2*>(ob + nt * 8) =
                __floats2half2_rn(C[nt][2] * s, C[nt][3] * s);
        }
    }
}

// ---------------- HMMA final GEMM K=64 + bias + tanh, transposed store
__global__ __launch_bounds__(128) void hgemm_final_kernel(
    const __half* __restrict__ in, const float* __restrict__ bias,
    float* __restrict__ out)
{
    const int lane = threadIdx.x & 31;
    const int g = lane >> 2, t = lane & 3;

    uint32_t B0[4][8], B1[4][8];
    const uint32_t* wp = reinterpret_cast<const uint32_t*>(g_Wft);
#pragma unroll
    for (int kk = 0; kk < 4; ++kk)
#pragma unroll
        for (int nt = 0; nt < 8; ++nt) {
            B0[kk][nt] = wp[((nt * 8 + g) * 64 + kk * 16 + t * 2) >> 1];
            B1[kk][nt] = wp[((nt * 8 + g) * 64 + kk * 16 + 8 + t * 2) >> 1];
        }
    float2 bv[8];
#pragma unroll
    for (int nt = 0; nt < 8; ++nt)
        bv[nt] = *reinterpret_cast<const float2*>(bias + nt * 8 + t * 2);

    const int warp = (blockIdx.x * blockDim.x + threadIdx.x) >> 5;
    const int nw   = (gridDim.x * blockDim.x) >> 5;
    for (int tile = warp; tile < NTILES; tile += nw) {
        const int rb = tile * 16;
        const uint32_t* ap = reinterpret_cast<const uint32_t*>(in + (size_t)rb * 64);

        float C[8][4];
#pragma unroll
        for (int nt = 0; nt < 8; ++nt) { C[nt][0] = C[nt][1] = C[nt][2] = C[nt][3] = 0.f; }
#pragma unroll
        for (int kk = 0; kk < 4; ++kk) {
            uint32_t a0 = ap[(g * 64 + kk * 16 + t * 2) >> 1];
            uint32_t a1 = ap[((g + 8) * 64 + kk * 16 + t * 2) >> 1];
            uint32_t a2 = ap[(g * 64 + kk * 16 + 8 + t * 2) >> 1];
            uint32_t a3 = ap[((g + 8) * 64 + kk * 16 + 8 + t * 2) >> 1];
#pragma unroll
            for (int nt = 0; nt < 8; ++nt)
                mma16816(C[nt], a0, a1, a2, a3, B0[kk][nt], B1[kk][nt]);
        }

        const int ra = rb + g, rbw = rb + g + 8;
        const int na = ra >> 6, ba = ra & 63;
        const int nb = rbw >> 6, bb = rbw & 63;
        float* oa = out + (size_t)ba * (NA * HD) + (size_t)na * 64 + t * 2;
        float* ob = out + (size_t)bb * (NA * HD) + (size_t)nb * 64 + t * 2;
#pragma unroll
        for (int nt = 0; nt < 8; ++nt) {
            *reinterpret_cast<float2*>(oa + nt * 8) =
                make_float2(tanhf(C[nt][0] + bv[nt].x), tanhf(C[nt][1] + bv[nt].y));
            *reinterpret_cast<float2*>(ob + nt * 8) =
                make_float2(tanhf(C[nt][2] + bv[nt].x), tanhf(C[nt][3] + bv[nt].y));
        }
    }
}

// ---------------------------------------------------------------------------

extern "C" void kernel_launch(void* const* d_in, const int* in_sizes, int n_in,
                              void* d_out, int out_size)
{
    const float* state = (const float*)d_in[0];
    const int*   ei    = (const int*)d_in[1];
    const float* W1  = (const float*)d_in[5];
    const float* b1  = (const float*)d_in[6];
    const float* W2  = (const float*)d_in[7];
    const float* b2  = (const float*)d_in[8];
    const float* W3  = (const float*)d_in[9];
    const float* b3  = (const float*)d_in[10];
    const float* g1  = (const float*)d_in[11];
    const float* be1 = (const float*)d_in[12];
    const float* g3  = (const float*)d_in[13];
    const float* be3 = (const float*)d_in[14];
    const float* Wf  = (const float*)d_in[15];
    const float* bf  = (const float*)d_in[16];
    float* out = (float*)d_out;

    const int E = in_sizes[1] / 2;

    __half *pH1h, *pH2h, *pH3h, *pPre, *pX, *pAX;
    cudaGetSymbolAddress((void**)&pH1h, g_h1h);
    cudaGetSymbolAddress((void**)&pH2h, g_h2h);
    cudaGetSymbolAddress((void**)&pH3h, g_h3h);
    cudaGetSymbolAddress((void**)&pPre, g_pre);
    cudaGetSymbolAddress((void**)&pX,   g_X);
    cudaGetSymbolAddress((void**)&pAX,  g_AX);

    __half* pW3t;
    cudaGetSymbolAddress((void**)&pW3t, g_W3t);
    int* pDeg;
    cudaGetSymbolAddress((void**)&pDeg, g_deg);

    // graph preprocessing (CSR by dst; self-loops emitted by scan),
    // weight fp16 prep merged into count
    cudaMemsetAsync(pDeg, 0, NA * sizeof(int));
    count_kernel<<<(E + 255) / 256, 256>>>(ei, E, W1, W2, W3, Wf);
    scan_kernel<<<1, 1024>>>();                       // rowptr/fillptr + dinv + self loops
    fill_transpose_kernel<<<(NA * BT + 255) / 256, 256>>>(ei, E, state);

    // conv1 = (A x) W1, + fused W2 GEMM producing conv2's pre-agg operand
    agg16_kernel<<<NA, 128>>>(pX, pAX);
    hgemm16_ln_w2_kernel<<<4736, 128>>>(pAX, b1, g1, be1, pH1h, pPre);

    // conv2: h2 = leaky(A pre + b2) + h1
    aggH_kernel<1><<<dim3(NA, 2), 128>>>(pPre, pH2h, b2, nullptr, nullptr);

    // conv3: h3 = leaky(LN(A (h2 W3) + b3)) + h1
    hgemm64_kernel<<<4736, 128>>>(pH2h, pW3t, pPre);
    aggH_kernel<2><<<dim3(NA, 2), 128>>>(pPre, pH3h, b3, g3, be3);

    // out = tanh(h3 Wf + bf), transposed back to [B, N*H]
    hgemm_final_kernel<<<4736, 128>>>(pH3h, bf, out);
}